// round 7
// baseline (speedup 1.0000x reference)
#include <cuda_runtime.h>
#include <cuda_bf16.h>
#include <math.h>
#include <stdint.h>

#define BB 4
#define SS 2048
#define EE 1024
#define HH 16
#define DD 64
#define ROWS (BB*SS)          // 8192

#define NEG_INF (__int_as_float(0xff800000))

// ---------------- scratch (device globals: no runtime allocation) ----------
__device__ __align__(16) __nv_bfloat16 g_xh[ROWS*EE];
__device__ __align__(16) __nv_bfloat16 g_xl[ROWS*EE];
__device__ __align__(16) __nv_bfloat16 g_qkvh[3u*ROWS*EE];
__device__ __align__(16) __nv_bfloat16 g_qkvl[3u*ROWS*EE];
__device__ __align__(16) __nv_bfloat16 g_ah[ROWS*EE];
__device__ __align__(16) __nv_bfloat16 g_al[ROWS*EE];
__device__ __align__(16) __nv_bfloat16 g_wh[4u*EE*EE];
__device__ __align__(16) __nv_bfloat16 g_wl[4u*EE*EE];

// ---------------------------------------------------------------------------
// fp32 -> bf16 hi/lo split
// ---------------------------------------------------------------------------
__global__ __launch_bounds__(256)
void split_kernel(const float4* __restrict__ in, uint2* __restrict__ hi,
                  uint2* __restrict__ lo, int n4)
{
    int i = blockIdx.x * blockDim.x + threadIdx.x;
    if (i >= n4) return;
    float4 v = in[i];
    float vv[4] = {v.x, v.y, v.z, v.w};
    unsigned hu[4], lu[4];
    #pragma unroll
    for (int j = 0; j < 4; ++j) {
        __nv_bfloat16 h = __float2bfloat16(vv[j]);
        float r = vv[j] - __bfloat162float(h);
        __nv_bfloat16 l = __float2bfloat16(r);
        hu[j] = (unsigned)__bfloat16_as_ushort(h);
        lu[j] = (unsigned)__bfloat16_as_ushort(l);
    }
    uint2 ho, lv;
    ho.x = hu[0] | (hu[1] << 16); ho.y = hu[2] | (hu[3] << 16);
    lv.x = lu[0] | (lu[1] << 16); lv.y = lu[2] | (lu[3] << 16);
    hi[i] = ho; lo[i] = lv;
}

// ---------------------------------------------------------------------------
// mma.sync helpers
// ---------------------------------------------------------------------------
__device__ __forceinline__ void cp16(uint32_t saddr, const void* gptr) {
    asm volatile("cp.async.cg.shared.global [%0], [%1], 16;"
                 :: "r"(saddr), "l"(gptr));
}
__device__ __forceinline__ void cp_commit() {
    asm volatile("cp.async.commit_group;" ::: "memory");
}
__device__ __forceinline__ void ldsm4(uint32_t* r, uint32_t addr) {
    asm volatile("ldmatrix.sync.aligned.m8n8.x4.shared.b16 {%0,%1,%2,%3}, [%4];"
                 : "=r"(r[0]), "=r"(r[1]), "=r"(r[2]), "=r"(r[3]) : "r"(addr));
}
__device__ __forceinline__ void ldsm4t(uint32_t* r, uint32_t addr) {
    asm volatile("ldmatrix.sync.aligned.m8n8.x4.trans.shared.b16 {%0,%1,%2,%3}, [%4];"
                 : "=r"(r[0]), "=r"(r[1]), "=r"(r[2]), "=r"(r[3]) : "r"(addr));
}
__device__ __forceinline__ void mma16816(float* c, const uint32_t* a, const uint32_t* b) {
    asm volatile(
        "mma.sync.aligned.m16n8k16.row.col.f32.bf16.bf16.f32 "
        "{%0,%1,%2,%3}, {%4,%5,%6,%7}, {%8,%9}, {%0,%1,%2,%3};"
        : "+f"(c[0]), "+f"(c[1]), "+f"(c[2]), "+f"(c[3])
        : "r"(a[0]), "r"(a[1]), "r"(a[2]), "r"(a[3]), "r"(b[0]), "r"(b[1]));
}
__device__ __forceinline__ void splitpack(float a, float b, uint32_t& hi, uint32_t& lo) {
    __nv_bfloat16 ha = __float2bfloat16(a), hb = __float2bfloat16(b);
    uint32_t hh = (uint32_t)__bfloat16_as_ushort(ha) |
                  ((uint32_t)__bfloat16_as_ushort(hb) << 16);
    __nv_bfloat16 la = __float2bfloat16(a - __bfloat162float(ha));
    __nv_bfloat16 lb = __float2bfloat16(b - __bfloat162float(hb));
    uint32_t ll = (uint32_t)__bfloat16_as_ushort(la) |
                  ((uint32_t)__bfloat16_as_ushort(lb) << 16);
    hi = hh; lo = ll;
}

#define STAGES 3
#define TILEB 16384
#define STAGEB (4*TILEB)     // 64 KB per stage
#define NKC (EE/64)

// ===========================================================================
// GEMM core: CTA tile 128x128, 512 threads / 16 warps (4x4), warp tile 32x32,
// 3-stage cp.async pipeline. bf16x3 accumulate. Template: QKV (wsel from
// blockIdx, split bf16 output) vs O (fp32 + bias output).
// ===========================================================================
template<bool QKV>
__global__ __launch_bounds__(512, 1)
void mma_gemm(const __nv_bfloat16* __restrict__ Ah, const __nv_bfloat16* __restrict__ Al,
              const __nv_bfloat16* __restrict__ Wh0, const __nv_bfloat16* __restrict__ Wl0,
              const float* __restrict__ bias, float* __restrict__ C,
              __nv_bfloat16* __restrict__ Ch0, __nv_bfloat16* __restrict__ Cl0)
{
    extern __shared__ char smem[];
    const uint32_t sb = (uint32_t)__cvta_generic_to_shared(smem);
    const int K = EE, N = EE;

    const int tid = threadIdx.x;
    const int w = tid >> 5, lane = tid & 31;
    const int wm = w & 3, wn = w >> 2;
    const int wsel = QKV ? (blockIdx.x >> 3) : 0;
    const int bm = blockIdx.y * 128;
    const int bn = QKV ? ((blockIdx.x & 7) * 128) : (blockIdx.x * 128);

    const __nv_bfloat16* Wh = Wh0 + (size_t)wsel * EE * EE;
    const __nv_bfloat16* Wl = Wl0 + (size_t)wsel * EE * EE;
    __nv_bfloat16* Ch = QKV ? (Ch0 + (size_t)wsel * ROWS * EE) : nullptr;
    __nv_bfloat16* Cl = QKV ? (Cl0 + (size_t)wsel * ROWS * EE) : nullptr;

    const __nv_bfloat16* gsrc[4] = {
        Ah + (size_t)bm * K, Al + (size_t)bm * K,
        Wh + (size_t)bn * K, Wl + (size_t)bn * K };

    // per-stage: 4 tiles x 1024 16B segs = 4096 segs over 512 threads (8 each)
    int lrow[8], ls8[8], ltile[8];
    uint32_t lsoff[8];
    #pragma unroll
    for (int i = 0; i < 8; ++i) {
        int idx = tid + i * 512;
        ltile[i] = idx >> 10;
        lrow[i] = (idx & 1023) >> 3; ls8[i] = idx & 7;
        lsoff[i] = (uint32_t)(ltile[i] * TILEB + lrow[i] * 128 +
                              ((ls8[i] * 16) ^ ((lrow[i] & 7) << 4)));
    }

    const int r8 = lane & 7, g = lane >> 3;
    const int arow = wm * 32 + r8 + (g & 1) * 8;
    const int acolg = (g >> 1) * 16;
    const uint32_t axor = (uint32_t)((arow & 7) << 4);
    const int brow = wn * 32 + r8 + (g >> 1) * 8;
    const int bcolg = (g & 1) * 16;
    const uint32_t bxor = (uint32_t)((brow & 7) << 4);

    float acc[2][4][4];
    #pragma unroll
    for (int a = 0; a < 2; ++a)
        #pragma unroll
        for (int b = 0; b < 4; ++b)
            #pragma unroll
            for (int c = 0; c < 4; ++c) acc[a][b][c] = 0.f;

    #pragma unroll
    for (int s = 0; s < STAGES - 1; ++s) {
        #pragma unroll
        for (int i = 0; i < 8; ++i)
            cp16(sb + s * STAGEB + lsoff[i],
                 gsrc[ltile[i]] + (size_t)lrow[i] * K + s * 64 + ls8[i] * 8);
        cp_commit();
    }

    for (int kc = 0; kc < NKC; ++kc) {
        asm volatile("cp.async.wait_group 1;" ::: "memory");
        __syncthreads();

        const int pf = kc + STAGES - 1;
        if (pf < NKC) {
            const int slot = pf % STAGES;
            #pragma unroll
            for (int i = 0; i < 8; ++i)
                cp16(sb + slot * STAGEB + lsoff[i],
                     gsrc[ltile[i]] + (size_t)lrow[i] * K + pf * 64 + ls8[i] * 8);
        }
        cp_commit();

        const uint32_t stg = sb + (uint32_t)((kc % STAGES) * STAGEB);
        const uint32_t bAh = stg, bAl = stg + TILEB, bWh = stg + 2*TILEB, bWl = stg + 3*TILEB;

        #pragma unroll
        for (int ks = 0; ks < 4; ++ks) {
            uint32_t aH[2][4], aL[2][4];
            const uint32_t colA = (uint32_t)((ks * 32 + acolg)) ^ axor;
            const uint32_t colB = (uint32_t)((ks * 32 + bcolg)) ^ bxor;
            #pragma unroll
            for (int mf = 0; mf < 2; ++mf) {
                const uint32_t ro = (uint32_t)((arow + mf * 16) * 128) + colA;
                ldsm4(aH[mf], bAh + ro);
                ldsm4(aL[mf], bAl + ro);
            }
            #pragma unroll
            for (int nf2 = 0; nf2 < 2; ++nf2) {
                uint32_t bH[4], bL[4];
                const uint32_t ro = (uint32_t)((brow + nf2 * 16) * 128) + colB;
                ldsm4(bH, bWh + ro);
                ldsm4(bL, bWl + ro);
                #pragma unroll
                for (int mf = 0; mf < 2; ++mf)
                    #pragma unroll
                    for (int j = 0; j < 2; ++j) {
                        float* c = acc[mf][nf2 * 2 + j];
                        mma16816(c, aH[mf], &bH[j * 2]);
                        mma16816(c, aH[mf], &bL[j * 2]);
                        mma16816(c, aL[mf], &bH[j * 2]);
                    }
            }
        }
        __syncthreads();
    }

    const int row0 = bm + wm * 32 + (lane >> 2);
    const int col0 = bn + wn * 32 + (lane & 3) * 2;
    #pragma unroll
    for (int mf = 0; mf < 2; ++mf)
        #pragma unroll
        for (int nf = 0; nf < 4; ++nf) {
            const int r = row0 + mf * 16;
            const int col = col0 + nf * 8;
            if (QKV) {
                uint32_t h0, l0, h1, l1;
                splitpack(acc[mf][nf][0], acc[mf][nf][1], h0, l0);
                splitpack(acc[mf][nf][2], acc[mf][nf][3], h1, l1);
                *(uint32_t*)&Ch[(size_t)r * N + col]       = h0;
                *(uint32_t*)&Cl[(size_t)r * N + col]       = l0;
                *(uint32_t*)&Ch[(size_t)(r + 8) * N + col] = h1;
                *(uint32_t*)&Cl[(size_t)(r + 8) * N + col] = l1;
            } else {
                float b0 = bias[col], b1 = bias[col + 1];
                float2 v0, v1;
                v0.x = acc[mf][nf][0] + b0; v0.y = acc[mf][nf][1] + b1;
                v1.x = acc[mf][nf][2] + b0; v1.y = acc[mf][nf][3] + b1;
                *(float2*)&C[(size_t)r * N + col]       = v0;
                *(float2*)&C[(size_t)(r + 8) * N + col] = v1;
            }
        }
}

// ---------------------------------------------------------------------------
// Tensor-core causal flash attention (unchanged from round 6).
// CTA: 256 q rows, 512 threads, kv chunks of 64, double-buffered cp.async.
// ---------------------------------------------------------------------------
#define FKVB 32768

__global__ __launch_bounds__(512, 1)
void flash_mma(const __nv_bfloat16* __restrict__ Qh, const __nv_bfloat16* __restrict__ Ql,
               const __nv_bfloat16* __restrict__ Kh, const __nv_bfloat16* __restrict__ Kl,
               const __nv_bfloat16* __restrict__ Vh, const __nv_bfloat16* __restrict__ Vl,
               __nv_bfloat16* __restrict__ Oh, __nv_bfloat16* __restrict__ Ol)
{
    extern __shared__ char smem[];
    const uint32_t sb = (uint32_t)__cvta_generic_to_shared(smem);
    const int tid = threadIdx.x, w = tid >> 5, lane = tid & 31;
    const int qt = (int)(gridDim.x - 1 - blockIdx.x);
    const int bh = blockIdx.y, b = bh >> 4, h = bh & 15;
    const size_t gbase = (size_t)(b * SS) * EE + h * 64;

    #pragma unroll
    for (int i = 0; i < 8; ++i) {
        int idx = tid + i * 512;
        int t = idx >> 11, rr = (idx & 2047) >> 3, s8 = idx & 7;
        const __nv_bfloat16* src = (t ? Ql : Qh) + gbase + (size_t)(qt * 256 + rr) * EE + s8 * 8;
        cp16(sb + t * 32768 + rr * 128 + (uint32_t)((s8 * 16) ^ ((rr & 7) << 4)), src);
    }
    cp_commit();

    const __nv_bfloat16* kv[4] = { Kh, Kl, Vh, Vl };

    {
        const uint32_t bufb = sb + 65536;
        #pragma unroll
        for (int i = 0; i < 4; ++i) {
            int idx = tid + i * 512;
            int t = idx >> 9, rr = (idx & 511) >> 3, s8 = idx & 7;
            cp16(bufb + t * 8192 + rr * 128 + (uint32_t)((s8 * 16) ^ ((rr & 7) << 4)),
                 kv[t] + gbase + (size_t)rr * EE + s8 * 8);
        }
        cp_commit();
    }

    const int r8 = lane & 7, g = lane >> 3;
    const int arow = w * 16 + r8 + (g & 1) * 8;
    const uint32_t axor = (uint32_t)((arow & 7) << 4);
    const int acolg = (g >> 1) * 16;
    const int brow = r8 + (g >> 1) * 8;
    const uint32_t bxor = (uint32_t)((brow & 7) << 4);
    const int bcolg = (g & 1) * 16;
    const int vrow = r8 + (g & 1) * 8;
    const uint32_t vxor = (uint32_t)((vrow & 7) << 4);
    const int vcolg = (g >> 1) * 16;

    float oacc[8][4];
    #pragma unroll
    for (int j = 0; j < 8; ++j)
        #pragma unroll
        for (int e = 0; e < 4; ++e) oacc[j][e] = 0.f;
    float m0 = NEG_INF, m1 = NEG_INF, l0 = 0.f, l1 = 0.f;

    const int nch = 4 * qt + 4;
    const int wminrow = qt * 256 + w * 16;

    for (int c = 0; c < nch; ++c) {
        if (c + 1 < nch) {
            const uint32_t bufb = sb + 65536 + (uint32_t)(((c + 1) & 1) * FKVB);
            #pragma unroll
            for (int i = 0; i < 4; ++i) {
                int idx = tid + i * 512;
                int t = idx >> 9, rr = (idx & 511) >> 3, s8 = idx & 7;
                cp16(bufb + t * 8192 + rr * 128 + (uint32_t)((s8 * 16) ^ ((rr & 7) << 4)),
                     kv[t] + gbase + (size_t)((c + 1) * 64 + rr) * EE + s8 * 8);
            }
        }
        cp_commit();
        asm volatile("cp.async.wait_group 1;" ::: "memory");
        __syncthreads();

        if (c * 64 <= wminrow + 15) {
            const uint32_t bufb = sb + 65536 + (uint32_t)((c & 1) * FKVB);
            float sacc[8][4];
            #pragma unroll
            for (int j = 0; j < 8; ++j)
                #pragma unroll
                for (int e = 0; e < 4; ++e) sacc[j][e] = 0.f;

            #pragma unroll
            for (int ks = 0; ks < 4; ++ks) {
                uint32_t aH[4], aL[4];
                const uint32_t ao = (uint32_t)(arow * 128) + ((uint32_t)(ks * 32 + acolg) ^ axor);
                ldsm4(aH, sb + ao);
                ldsm4(aL, sb + 32768 + ao);
                const uint32_t colB = (uint32_t)(ks * 32 + bcolg) ^ bxor;
                #pragma unroll
                for (int nf2 = 0; nf2 < 4; ++nf2) {
                    uint32_t bH[4], bL[4];
                    const uint32_t ro = (uint32_t)((brow + nf2 * 16) * 128) + colB;
                    ldsm4(bH, bufb + ro);
                    ldsm4(bL, bufb + 8192 + ro);
                    #pragma unroll
                    for (int j = 0; j < 2; ++j) {
                        float* cc = sacc[nf2 * 2 + j];
                        mma16816(cc, aH, &bH[j * 2]);
                        mma16816(cc, aH, &bL[j * 2]);
                        mma16816(cc, aL, &bH[j * 2]);
                    }
                }
            }

            const int row0 = wminrow + (lane >> 2);
            if (c * 64 + 63 > wminrow) {
                #pragma unroll
                for (int j = 0; j < 8; ++j) {
                    int col = c * 64 + j * 8 + (lane & 3) * 2;
                    if (col     > row0)     sacc[j][0] = NEG_INF;
                    if (col + 1 > row0)     sacc[j][1] = NEG_INF;
                    if (col     > row0 + 8) sacc[j][2] = NEG_INF;
                    if (col + 1 > row0 + 8) sacc[j][3] = NEG_INF;
                }
            }
            float t0 = NEG_INF, t1 = NEG_INF;
            #pragma unroll
            for (int j = 0; j < 8; ++j) {
                sacc[j][0] *= 0.125f; sacc[j][1] *= 0.125f;
                sacc[j][2] *= 0.125f; sacc[j][3] *= 0.125f;
                t0 = fmaxf(t0, fmaxf(sacc[j][0], sacc[j][1]));
                t1 = fmaxf(t1, fmaxf(sacc[j][2], sacc[j][3]));
            }
            t0 = fmaxf(t0, __shfl_xor_sync(0xffffffffu, t0, 1));
            t0 = fmaxf(t0, __shfl_xor_sync(0xffffffffu, t0, 2));
            t1 = fmaxf(t1, __shfl_xor_sync(0xffffffffu, t1, 1));
            t1 = fmaxf(t1, __shfl_xor_sync(0xffffffffu, t1, 2));

            const float mn0 = fmaxf(m0, t0), mn1 = fmaxf(m1, t1);
            const float cr0 = __expf(m0 - mn0), cr1 = __expf(m1 - mn1);
            float s0 = 0.f, s1 = 0.f;
            #pragma unroll
            for (int j = 0; j < 8; ++j) {
                float p0 = __expf(sacc[j][0] - mn0); sacc[j][0] = p0; s0 += p0;
                float p1 = __expf(sacc[j][1] - mn0); sacc[j][1] = p1; s0 += p1;
                float p2 = __expf(sacc[j][2] - mn1); sacc[j][2] = p2; s1 += p2;
                float p3 = __expf(sacc[j][3] - mn1); sacc[j][3] = p3; s1 += p3;
            }
            s0 += __shfl_xor_sync(0xffffffffu, s0, 1);
            s0 += __shfl_xor_sync(0xffffffffu, s0, 2);
            s1 += __shfl_xor_sync(0xffffffffu, s1, 1);
            s1 += __shfl_xor_sync(0xffffffffu, s1, 2);
            l0 = l0 * cr0 + s0; l1 = l1 * cr1 + s1;
            m0 = mn0; m1 = mn1;
            #pragma unroll
            for (int j = 0; j < 8; ++j) {
                oacc[j][0] *= cr0; oacc[j][1] *= cr0;
                oacc[j][2] *= cr1; oacc[j][3] *= cr1;
            }

            #pragma unroll
            for (int ks = 0; ks < 4; ++ks) {
                uint32_t aPh[4], aPl[4];
                splitpack(sacc[2*ks][0],   sacc[2*ks][1],   aPh[0], aPl[0]);
                splitpack(sacc[2*ks][2],   sacc[2*ks][3],   aPh[1], aPl[1]);
                splitpack(sacc[2*ks+1][0], sacc[2*ks+1][1], aPh[2], aPl[2]);
                splitpack(sacc[2*ks+1][2], sacc[2*ks+1][3], aPh[3], aPl[3]);
                const uint32_t rbase = (uint32_t)((ks * 16 + vrow) * 128);
                #pragma unroll
                for (int nf2 = 0; nf2 < 4; ++nf2) {
                    uint32_t vH[4], vL[4];
                    const uint32_t vo = rbase + ((uint32_t)(nf2 * 32 + vcolg) ^ vxor);
                    ldsm4t(vH, bufb + 16384 + vo);
                    ldsm4t(vL, bufb + 24576 + vo);
                    #pragma unroll
                    for (int j = 0; j < 2; ++j) {
                        float* cc = oacc[nf2 * 2 + j];
                        mma16816(cc, aPh, &vH[j * 2]);
                        mma16816(cc, aPh, &vL[j * 2]);
                        mma16816(cc, aPl, &vH[j * 2]);
                    }
                }
            }
        }
        __syncthreads();
    }

    const float inv0 = 1.f / l0, inv1 = 1.f / l1;
    const int orow = qt * 256 + w * 16 + (lane >> 2);
    const int ocol = (lane & 3) * 2;
    #pragma unroll
    for (int j = 0; j < 8; ++j) {
        uint32_t h0, lo0, h1, lo1;
        splitpack(oacc[j][0] * inv0, oacc[j][1] * inv0, h0, lo0);
        splitpack(oacc[j][2] * inv1, oacc[j][3] * inv1, h1, lo1);
        size_t a0 = gbase + (size_t)orow * EE + j * 8 + ocol;
        size_t a1 = a0 + (size_t)8 * EE;
        *(uint32_t*)&Oh[a0] = h0; *(uint32_t*)&Ol[a0] = lo0;
        *(uint32_t*)&Oh[a1] = h1; *(uint32_t*)&Ol[a1] = lo1;
    }
}

// ---------------------------------------------------------------------------
extern "C" void kernel_launch(void* const* d_in, const int* in_sizes, int n_in,
                              void* d_out, int out_size)
{
    const float* x   = (const float*)d_in[0];
    const float* w_q = (const float*)d_in[2];
    const float* w_k = (const float*)d_in[3];
    const float* w_v = (const float*)d_in[4];
    const float* w_o = (const float*)d_in[5];
    const float* b_o = (const float*)d_in[6];
    float* out = (float*)d_out;

    __nv_bfloat16 *xh, *xl, *qkvh, *qkvl, *ah, *al, *wh, *wl;
    cudaGetSymbolAddress((void**)&xh,   g_xh);
    cudaGetSymbolAddress((void**)&xl,   g_xl);
    cudaGetSymbolAddress((void**)&qkvh, g_qkvh);
    cudaGetSymbolAddress((void**)&qkvl, g_qkvl);
    cudaGetSymbolAddress((void**)&ah,   g_ah);
    cudaGetSymbolAddress((void**)&al,   g_al);
    cudaGetSymbolAddress((void**)&wh,   g_wh);
    cudaGetSymbolAddress((void**)&wl,   g_wl);

    const int n4x = ROWS * EE / 4;
    const int n4w = EE * EE / 4;
    const float* ws[4] = {w_q, w_k, w_v, w_o};
    for (int i = 0; i < 4; ++i)
        split_kernel<<<(n4w + 255) / 256, 256>>>((const float4*)ws[i],
                                                 (uint2*)(wh + (size_t)i * EE * EE),
                                                 (uint2*)(wl + (size_t)i * EE * EE), n4w);
    split_kernel<<<(n4x + 255) / 256, 256>>>((const float4*)x, (uint2*)xh, (uint2*)xl, n4x);

    const int gsmem = STAGES * STAGEB;   // 196608
    cudaFuncSetAttribute(mma_gemm<true>,  cudaFuncAttributeMaxDynamicSharedMemorySize, gsmem);
    cudaFuncSetAttribute(mma_gemm<false>, cudaFuncAttributeMaxDynamicSharedMemorySize, gsmem);
    dim3 gq(3 * EE / 128, ROWS / 128);
    mma_gemm<true><<<gq, 512, gsmem>>>(xh, xl, wh, wl, nullptr, nullptr, qkvh, qkvl);

    const size_t TS = (size_t)ROWS * EE;
    const int fsmem = 65536 + 2 * FKVB;  // 131072
    cudaFuncSetAttribute(flash_mma, cudaFuncAttributeMaxDynamicSharedMemorySize, fsmem);
    dim3 fgrid(SS / 256, BB * HH);
    flash_mma<<<fgrid, 512, fsmem>>>(qkvh, qkvl, qkvh + TS, qkvl + TS,
                                     qkvh + 2 * TS, qkvl + 2 * TS, ah, al);

    dim3 gg(EE / 128, ROWS / 128);
    mma_gemm<false><<<gg, 512, gsmem>>>(ah, al, wh + 3ull*EE*EE, wl + 3ull*EE*EE,
                                        b_o, out, nullptr, nullptr);
}

// round 8
// speedup vs baseline: 1.0512x; 1.0512x over previous
#include <cuda_runtime.h>
#include <cuda_bf16.h>
#include <math.h>
#include <stdint.h>

#define BB 4
#define SS 2048
#define EE 1024
#define HH 16
#define DD 64
#define ROWS (BB*SS)          // 8192

#define NEG_INF (__int_as_float(0xff800000))

// ---------------- scratch (device globals: no runtime allocation) ----------
__device__ __align__(16) __nv_bfloat16 g_xh[ROWS*EE];
__device__ __align__(16) __nv_bfloat16 g_xl[ROWS*EE];
__device__ __align__(16) __nv_bfloat16 g_qkvh[3u*ROWS*EE];
__device__ __align__(16) __nv_bfloat16 g_qkvl[3u*ROWS*EE];
__device__ __align__(16) __nv_bfloat16 g_ah[ROWS*EE];
__device__ __align__(16) __nv_bfloat16 g_al[ROWS*EE];
__device__ __align__(16) __nv_bfloat16 g_wh[4u*EE*EE];
__device__ __align__(16) __nv_bfloat16 g_wl[4u*EE*EE];

// ---------------------------------------------------------------------------
// fp32 -> bf16 hi/lo split
// ---------------------------------------------------------------------------
__global__ __launch_bounds__(256)
void split_kernel(const float4* __restrict__ in, uint2* __restrict__ hi,
                  uint2* __restrict__ lo, int n4)
{
    int i = blockIdx.x * blockDim.x + threadIdx.x;
    if (i >= n4) return;
    float4 v = in[i];
    float vv[4] = {v.x, v.y, v.z, v.w};
    unsigned hu[4], lu[4];
    #pragma unroll
    for (int j = 0; j < 4; ++j) {
        __nv_bfloat16 h = __float2bfloat16(vv[j]);
        float r = vv[j] - __bfloat162float(h);
        __nv_bfloat16 l = __float2bfloat16(r);
        hu[j] = (unsigned)__bfloat16_as_ushort(h);
        lu[j] = (unsigned)__bfloat16_as_ushort(l);
    }
    uint2 ho, lv;
    ho.x = hu[0] | (hu[1] << 16); ho.y = hu[2] | (hu[3] << 16);
    lv.x = lu[0] | (lu[1] << 16); lv.y = lu[2] | (lu[3] << 16);
    hi[i] = ho; lo[i] = lv;
}

// ---------------------------------------------------------------------------
// mma.sync helpers
// ---------------------------------------------------------------------------
__device__ __forceinline__ void cp16(uint32_t saddr, const void* gptr) {
    asm volatile("cp.async.cg.shared.global [%0], [%1], 16;"
                 :: "r"(saddr), "l"(gptr));
}
__device__ __forceinline__ void cp_commit() {
    asm volatile("cp.async.commit_group;" ::: "memory");
}
__device__ __forceinline__ void ldsm4(uint32_t* r, uint32_t addr) {
    asm volatile("ldmatrix.sync.aligned.m8n8.x4.shared.b16 {%0,%1,%2,%3}, [%4];"
                 : "=r"(r[0]), "=r"(r[1]), "=r"(r[2]), "=r"(r[3]) : "r"(addr));
}
__device__ __forceinline__ void ldsm4t(uint32_t* r, uint32_t addr) {
    asm volatile("ldmatrix.sync.aligned.m8n8.x4.trans.shared.b16 {%0,%1,%2,%3}, [%4];"
                 : "=r"(r[0]), "=r"(r[1]), "=r"(r[2]), "=r"(r[3]) : "r"(addr));
}
__device__ __forceinline__ void mma16816(float* c, const uint32_t* a, const uint32_t* b) {
    asm volatile(
        "mma.sync.aligned.m16n8k16.row.col.f32.bf16.bf16.f32 "
        "{%0,%1,%2,%3}, {%4,%5,%6,%7}, {%8,%9}, {%0,%1,%2,%3};"
        : "+f"(c[0]), "+f"(c[1]), "+f"(c[2]), "+f"(c[3])
        : "r"(a[0]), "r"(a[1]), "r"(a[2]), "r"(a[3]), "r"(b[0]), "r"(b[1]));
}
__device__ __forceinline__ void splitpack(float a, float b, uint32_t& hi, uint32_t& lo) {
    __nv_bfloat16 ha = __float2bfloat16(a), hb = __float2bfloat16(b);
    uint32_t hh = (uint32_t)__bfloat16_as_ushort(ha) |
                  ((uint32_t)__bfloat16_as_ushort(hb) << 16);
    __nv_bfloat16 la = __float2bfloat16(a - __bfloat162float(ha));
    __nv_bfloat16 lb = __float2bfloat16(b - __bfloat162float(hb));
    uint32_t ll = (uint32_t)__bfloat16_as_ushort(la) |
                  ((uint32_t)__bfloat16_as_ushort(lb) << 16);
    hi = hh; lo = ll;
}

#define NKC (EE/64)          // 16 k-chunks

// ===========================================================================
// GEMM core v3: CTA tile 128x256, 8 warps (2x4), warp tile 64x64,
// 2-stage cp.async double buffer (96 KB/stage).
// smem stage: Ah[16K] Al[16K] Bh[32K] Bl[32K]
// ===========================================================================
#define OF_AL 16384
#define OF_BH 32768
#define OF_BL 65536
#define GSTAGE 98304

template<bool QKV>
__global__ __launch_bounds__(256, 1)
void mma_gemm(const __nv_bfloat16* __restrict__ Ah0, const __nv_bfloat16* __restrict__ Al0,
              const __nv_bfloat16* __restrict__ Wh0, const __nv_bfloat16* __restrict__ Wl0,
              const float* __restrict__ bias, float* __restrict__ C,
              __nv_bfloat16* __restrict__ Ch0, __nv_bfloat16* __restrict__ Cl0)
{
    extern __shared__ char smem[];
    const uint32_t sb = (uint32_t)__cvta_generic_to_shared(smem);
    const int K = EE, N = EE;

    const int tid = threadIdx.x;
    const int w = tid >> 5, lane = tid & 31;
    const int wm = w & 1, wn = w >> 1;               // 2 x 4 warp grid
    const int wsel = QKV ? (blockIdx.x >> 2) : 0;
    const int bm = blockIdx.y * 128;
    const int bn = QKV ? ((blockIdx.x & 3) * 256) : (blockIdx.x * 256);

    const __nv_bfloat16* Ahp = Ah0 + (size_t)bm * K;
    const __nv_bfloat16* Alp = Al0 + (size_t)bm * K;
    const __nv_bfloat16* Bhp = Wh0 + (size_t)wsel * EE * EE + (size_t)bn * K;
    const __nv_bfloat16* Blp = Wl0 + (size_t)wsel * EE * EE + (size_t)bn * K;
    __nv_bfloat16* Ch = QKV ? (Ch0 + (size_t)wsel * ROWS * EE) : nullptr;
    __nv_bfloat16* Cl = QKV ? (Cl0 + (size_t)wsel * ROWS * EE) : nullptr;

    // ldmatrix geometry
    const int r8 = lane & 7, g = lane >> 3;
    const int arow = wm * 64 + r8 + (g & 1) * 8;     // + mf*16
    const int acolg = (g >> 1) * 16;
    const uint32_t axor = (uint32_t)((arow & 7) << 4);
    const int brow = wn * 64 + r8 + (g >> 1) * 8;    // + nf2*16
    const int bcolg = (g & 1) * 16;
    const uint32_t bxor = (uint32_t)((brow & 7) << 4);

    float acc[4][8][4];
    #pragma unroll
    for (int a = 0; a < 4; ++a)
        #pragma unroll
        for (int b = 0; b < 8; ++b)
            #pragma unroll
            for (int c = 0; c < 4; ++c) acc[a][b][c] = 0.f;

    // stage loader: 6144 16B segs (Ah 1024 | Al 1024 | Bh 2048 | Bl 2048)
    auto load_stage = [&](int slot, int kc) {
        const uint32_t sbase = sb + (uint32_t)(slot * GSTAGE);
        #pragma unroll
        for (int i = 0; i < 24; ++i) {
            int idx = tid + i * 256;
            const __nv_bfloat16* src;
            uint32_t toff; int local;
            if (i < 4)       { local = idx;        src = Ahp; toff = 0; }
            else if (i < 8)  { local = idx - 1024; src = Alp; toff = OF_AL; }
            else if (i < 16) { local = idx - 2048; src = Bhp; toff = OF_BH; }
            else             { local = idx - 4096; src = Blp; toff = OF_BL; }
            int row = local >> 3, s8 = local & 7;
            cp16(sbase + toff + (uint32_t)(row * 128 + ((s8 * 16) ^ ((row & 7) << 4))),
                 src + (size_t)row * K + kc * 64 + s8 * 8);
        }
        cp_commit();
    };

    load_stage(0, 0);

    for (int kc = 0; kc < NKC; ++kc) {
        if (kc + 1 < NKC) {
            load_stage((kc + 1) & 1, kc + 1);
            asm volatile("cp.async.wait_group 1;" ::: "memory");
        } else {
            asm volatile("cp.async.wait_group 0;" ::: "memory");
        }
        __syncthreads();

        const uint32_t stg = sb + (uint32_t)((kc & 1) * GSTAGE);

        #pragma unroll
        for (int ks = 0; ks < 4; ++ks) {
            uint32_t aH[4][4], aL[4][4];
            const uint32_t colA = (uint32_t)(ks * 32 + acolg) ^ axor;
            const uint32_t colB = (uint32_t)(ks * 32 + bcolg) ^ bxor;
            #pragma unroll
            for (int mf = 0; mf < 4; ++mf) {
                const uint32_t ro = (uint32_t)((arow + mf * 16) * 128) + colA;
                ldsm4(aH[mf], stg + ro);
                ldsm4(aL[mf], stg + OF_AL + ro);
            }
            #pragma unroll
            for (int nf2 = 0; nf2 < 4; ++nf2) {
                uint32_t bH[4], bL[4];
                const uint32_t ro = (uint32_t)((brow + nf2 * 16) * 128) + colB;
                ldsm4(bH, stg + OF_BH + ro);
                ldsm4(bL, stg + OF_BL + ro);
                #pragma unroll
                for (int mf = 0; mf < 4; ++mf)
                    #pragma unroll
                    for (int j = 0; j < 2; ++j) {
                        float* c = acc[mf][nf2 * 2 + j];
                        mma16816(c, aH[mf], &bH[j * 2]);
                        mma16816(c, aH[mf], &bL[j * 2]);
                        mma16816(c, aL[mf], &bH[j * 2]);
                    }
            }
        }
        __syncthreads();
    }

    const int row0 = bm + wm * 64 + (lane >> 2);
    const int col0 = bn + wn * 64 + (lane & 3) * 2;
    #pragma unroll
    for (int mf = 0; mf < 4; ++mf)
        #pragma unroll
        for (int nf = 0; nf < 8; ++nf) {
            const int r = row0 + mf * 16;
            const int col = col0 + nf * 8;
            if (QKV) {
                uint32_t h0, l0, h1, l1;
                splitpack(acc[mf][nf][0], acc[mf][nf][1], h0, l0);
                splitpack(acc[mf][nf][2], acc[mf][nf][3], h1, l1);
                *(uint32_t*)&Ch[(size_t)r * N + col]       = h0;
                *(uint32_t*)&Cl[(size_t)r * N + col]       = l0;
                *(uint32_t*)&Ch[(size_t)(r + 8) * N + col] = h1;
                *(uint32_t*)&Cl[(size_t)(r + 8) * N + col] = l1;
            } else {
                float b0 = bias[col], b1 = bias[col + 1];
                float2 v0, v1;
                v0.x = acc[mf][nf][0] + b0; v0.y = acc[mf][nf][1] + b1;
                v1.x = acc[mf][nf][2] + b0; v1.y = acc[mf][nf][3] + b1;
                *(float2*)&C[(size_t)r * N + col]       = v0;
                *(float2*)&C[(size_t)(r + 8) * N + col] = v1;
            }
        }
}

// ---------------------------------------------------------------------------
// Tensor-core causal flash attention (round-6 version, unchanged).
// CTA: 256 q rows, 512 threads, kv chunks of 64, double-buffered cp.async.
// ---------------------------------------------------------------------------
#define FKVB 32768

__global__ __launch_bounds__(512, 1)
void flash_mma(const __nv_bfloat16* __restrict__ Qh, const __nv_bfloat16* __restrict__ Ql,
               const __nv_bfloat16* __restrict__ Kh, const __nv_bfloat16* __restrict__ Kl,
               const __nv_bfloat16* __restrict__ Vh, const __nv_bfloat16* __restrict__ Vl,
               __nv_bfloat16* __restrict__ Oh, __nv_bfloat16* __restrict__ Ol)
{
    extern __shared__ char smem[];
    const uint32_t sb = (uint32_t)__cvta_generic_to_shared(smem);
    const int tid = threadIdx.x, w = tid >> 5, lane = tid & 31;
    const int qt = (int)(gridDim.x - 1 - blockIdx.x);
    const int bh = blockIdx.y, b = bh >> 4, h = bh & 15;
    const size_t gbase = (size_t)(b * SS) * EE + h * 64;

    #pragma unroll
    for (int i = 0; i < 8; ++i) {
        int idx = tid + i * 512;
        int t = idx >> 11, rr = (idx & 2047) >> 3, s8 = idx & 7;
        const __nv_bfloat16* src = (t ? Ql : Qh) + gbase + (size_t)(qt * 256 + rr) * EE + s8 * 8;
        cp16(sb + t * 32768 + rr * 128 + (uint32_t)((s8 * 16) ^ ((rr & 7) << 4)), src);
    }
    cp_commit();

    const __nv_bfloat16* kv[4] = { Kh, Kl, Vh, Vl };

    {
        const uint32_t bufb = sb + 65536;
        #pragma unroll
        for (int i = 0; i < 4; ++i) {
            int idx = tid + i * 512;
            int t = idx >> 9, rr = (idx & 511) >> 3, s8 = idx & 7;
            cp16(bufb + t * 8192 + rr * 128 + (uint32_t)((s8 * 16) ^ ((rr & 7) << 4)),
                 kv[t] + gbase + (size_t)rr * EE + s8 * 8);
        }
        cp_commit();
    }

    const int r8 = lane & 7, g = lane >> 3;
    const int arow = w * 16 + r8 + (g & 1) * 8;
    const uint32_t axor = (uint32_t)((arow & 7) << 4);
    const int acolg = (g >> 1) * 16;
    const int brow = r8 + (g >> 1) * 8;
    const uint32_t bxor = (uint32_t)((brow & 7) << 4);
    const int bcolg = (g & 1) * 16;
    const int vrow = r8 + (g & 1) * 8;
    const uint32_t vxor = (uint32_t)((vrow & 7) << 4);
    const int vcolg = (g >> 1) * 16;

    float oacc[8][4];
    #pragma unroll
    for (int j = 0; j < 8; ++j)
        #pragma unroll
        for (int e = 0; e < 4; ++e) oacc[j][e] = 0.f;
    float m0 = NEG_INF, m1 = NEG_INF, l0 = 0.f, l1 = 0.f;

    const int nch = 4 * qt + 4;
    const int wminrow = qt * 256 + w * 16;

    for (int c = 0; c < nch; ++c) {
        if (c + 1 < nch) {
            const uint32_t bufb = sb + 65536 + (uint32_t)(((c + 1) & 1) * FKVB);
            #pragma unroll
            for (int i = 0; i < 4; ++i) {
                int idx = tid + i * 512;
                int t = idx >> 9, rr = (idx & 511) >> 3, s8 = idx & 7;
                cp16(bufb + t * 8192 + rr * 128 + (uint32_t)((s8 * 16) ^ ((rr & 7) << 4)),
                     kv[t] + gbase + (size_t)((c + 1) * 64 + rr) * EE + s8 * 8);
            }
        }
        cp_commit();
        asm volatile("cp.async.wait_group 1;" ::: "memory");
        __syncthreads();

        if (c * 64 <= wminrow + 15) {
            const uint32_t bufb = sb + 65536 + (uint32_t)((c & 1) * FKVB);
            float sacc[8][4];
            #pragma unroll
            for (int j = 0; j < 8; ++j)
                #pragma unroll
                for (int e = 0; e < 4; ++e) sacc[j][e] = 0.f;

            #pragma unroll
            for (int ks = 0; ks < 4; ++ks) {
                uint32_t aH[4], aL[4];
                const uint32_t ao = (uint32_t)(arow * 128) + ((uint32_t)(ks * 32 + acolg) ^ axor);
                ldsm4(aH, sb + ao);
                ldsm4(aL, sb + 32768 + ao);
                const uint32_t colB = (uint32_t)(ks * 32 + bcolg) ^ bxor;
                #pragma unroll
                for (int nf2 = 0; nf2 < 4; ++nf2) {
                    uint32_t bH[4], bL[4];
                    const uint32_t ro = (uint32_t)((brow + nf2 * 16) * 128) + colB;
                    ldsm4(bH, bufb + ro);
                    ldsm4(bL, bufb + 8192 + ro);
                    #pragma unroll
                    for (int j = 0; j < 2; ++j) {
                        float* cc = sacc[nf2 * 2 + j];
                        mma16816(cc, aH, &bH[j * 2]);
                        mma16816(cc, aH, &bL[j * 2]);
                        mma16816(cc, aL, &bH[j * 2]);
                    }
                }
            }

            const int row0 = wminrow + (lane >> 2);
            if (c * 64 + 63 > wminrow) {
                #pragma unroll
                for (int j = 0; j < 8; ++j) {
                    int col = c * 64 + j * 8 + (lane & 3) * 2;
                    if (col     > row0)     sacc[j][0] = NEG_INF;
                    if (col + 1 > row0)     sacc[j][1] = NEG_INF;
                    if (col     > row0 + 8) sacc[j][2] = NEG_INF;
                    if (col + 1 > row0 + 8) sacc[j][3] = NEG_INF;
                }
            }
            float t0 = NEG_INF, t1 = NEG_INF;
            #pragma unroll
            for (int j = 0; j < 8; ++j) {
                sacc[j][0] *= 0.125f; sacc[j][1] *= 0.125f;
                sacc[j][2] *= 0.125f; sacc[j][3] *= 0.125f;
                t0 = fmaxf(t0, fmaxf(sacc[j][0], sacc[j][1]));
                t1 = fmaxf(t1, fmaxf(sacc[j][2], sacc[j][3]));
            }
            t0 = fmaxf(t0, __shfl_xor_sync(0xffffffffu, t0, 1));
            t0 = fmaxf(t0, __shfl_xor_sync(0xffffffffu, t0, 2));
            t1 = fmaxf(t1, __shfl_xor_sync(0xffffffffu, t1, 1));
            t1 = fmaxf(t1, __shfl_xor_sync(0xffffffffu, t1, 2));

            const float mn0 = fmaxf(m0, t0), mn1 = fmaxf(m1, t1);
            const float cr0 = __expf(m0 - mn0), cr1 = __expf(m1 - mn1);
            float s0 = 0.f, s1 = 0.f;
            #pragma unroll
            for (int j = 0; j < 8; ++j) {
                float p0 = __expf(sacc[j][0] - mn0); sacc[j][0] = p0; s0 += p0;
                float p1 = __expf(sacc[j][1] - mn0); sacc[j][1] = p1; s0 += p1;
                float p2 = __expf(sacc[j][2] - mn1); sacc[j][2] = p2; s1 += p2;
                float p3 = __expf(sacc[j][3] - mn1); sacc[j][3] = p3; s1 += p3;
            }
            s0 += __shfl_xor_sync(0xffffffffu, s0, 1);
            s0 += __shfl_xor_sync(0xffffffffu, s0, 2);
            s1 += __shfl_xor_sync(0xffffffffu, s1, 1);
            s1 += __shfl_xor_sync(0xffffffffu, s1, 2);
            l0 = l0 * cr0 + s0; l1 = l1 * cr1 + s1;
            m0 = mn0; m1 = mn1;
            #pragma unroll
            for (int j = 0; j < 8; ++j) {
                oacc[j][0] *= cr0; oacc[j][1] *= cr0;
                oacc[j][2] *= cr1; oacc[j][3] *= cr1;
            }

            #pragma unroll
            for (int ks = 0; ks < 4; ++ks) {
                uint32_t aPh[4], aPl[4];
                splitpack(sacc[2*ks][0],   sacc[2*ks][1],   aPh[0], aPl[0]);
                splitpack(sacc[2*ks][2],   sacc[2*ks][3],   aPh[1], aPl[1]);
                splitpack(sacc[2*ks+1][0], sacc[2*ks+1][1], aPh[2], aPl[2]);
                splitpack(sacc[2*ks+1][2], sacc[2*ks+1][3], aPh[3], aPl[3]);
                const uint32_t rbase = (uint32_t)((ks * 16 + vrow) * 128);
                #pragma unroll
                for (int nf2 = 0; nf2 < 4; ++nf2) {
                    uint32_t vH[4], vL[4];
                    const uint32_t vo = rbase + ((uint32_t)(nf2 * 32 + vcolg) ^ vxor);
                    ldsm4t(vH, bufb + 16384 + vo);
                    ldsm4t(vL, bufb + 24576 + vo);
                    #pragma unroll
                    for (int j = 0; j < 2; ++j) {
                        float* cc = oacc[nf2 * 2 + j];
                        mma16816(cc, aPh, &vH[j * 2]);
                        mma16816(cc, aPh, &vL[j * 2]);
                        mma16816(cc, aPl, &vH[j * 2]);
                    }
                }
            }
        }
        __syncthreads();
    }

    const float inv0 = 1.f / l0, inv1 = 1.f / l1;
    const int orow = qt * 256 + w * 16 + (lane >> 2);
    const int ocol = (lane & 3) * 2;
    #pragma unroll
    for (int j = 0; j < 8; ++j) {
        uint32_t h0, lo0, h1, lo1;
        splitpack(oacc[j][0] * inv0, oacc[j][1] * inv0, h0, lo0);
        splitpack(oacc[j][2] * inv1, oacc[j][3] * inv1, h1, lo1);
        size_t a0 = gbase + (size_t)orow * EE + j * 8 + ocol;
        size_t a1 = a0 + (size_t)8 * EE;
        *(uint32_t*)&Oh[a0] = h0; *(uint32_t*)&Ol[a0] = lo0;
        *(uint32_t*)&Oh[a1] = h1; *(uint32_t*)&Ol[a1] = lo1;
    }
}

// ---------------------------------------------------------------------------
extern "C" void kernel_launch(void* const* d_in, const int* in_sizes, int n_in,
                              void* d_out, int out_size)
{
    const float* x   = (const float*)d_in[0];
    const float* w_q = (const float*)d_in[2];
    const float* w_k = (const float*)d_in[3];
    const float* w_v = (const float*)d_in[4];
    const float* w_o = (const float*)d_in[5];
    const float* b_o = (const float*)d_in[6];
    float* out = (float*)d_out;

    __nv_bfloat16 *xh, *xl, *qkvh, *qkvl, *ah, *al, *wh, *wl;
    cudaGetSymbolAddress((void**)&xh,   g_xh);
    cudaGetSymbolAddress((void**)&xl,   g_xl);
    cudaGetSymbolAddress((void**)&qkvh, g_qkvh);
    cudaGetSymbolAddress((void**)&qkvl, g_qkvl);
    cudaGetSymbolAddress((void**)&ah,   g_ah);
    cudaGetSymbolAddress((void**)&al,   g_al);
    cudaGetSymbolAddress((void**)&wh,   g_wh);
    cudaGetSymbolAddress((void**)&wl,   g_wl);

    const int n4x = ROWS * EE / 4;
    const int n4w = EE * EE / 4;
    const float* ws[4] = {w_q, w_k, w_v, w_o};
    for (int i = 0; i < 4; ++i)
        split_kernel<<<(n4w + 255) / 256, 256>>>((const float4*)ws[i],
                                                 (uint2*)(wh + (size_t)i * EE * EE),
                                                 (uint2*)(wl + (size_t)i * EE * EE), n4w);
    split_kernel<<<(n4x + 255) / 256, 256>>>((const float4*)x, (uint2*)xh, (uint2*)xl, n4x);

    const int gsmem = 2 * GSTAGE;        // 196608
    cudaFuncSetAttribute(mma_gemm<true>,  cudaFuncAttributeMaxDynamicSharedMemorySize, gsmem);
    cudaFuncSetAttribute(mma_gemm<false>, cudaFuncAttributeMaxDynamicSharedMemorySize, gsmem);
    dim3 gq(3 * EE / 256, ROWS / 128);   // (12, 64)
    mma_gemm<true><<<gq, 256, gsmem>>>(xh, xl, wh, wl, nullptr, nullptr, qkvh, qkvl);

    const size_t TS = (size_t)ROWS * EE;
    const int fsmem = 65536 + 2 * FKVB;  // 131072
    cudaFuncSetAttribute(flash_mma, cudaFuncAttributeMaxDynamicSharedMemorySize, fsmem);
    dim3 fgrid(SS / 256, BB * HH);
    flash_mma<<<fgrid, 512, fsmem>>>(qkvh, qkvl, qkvh + TS, qkvl + TS,
                                     qkvh + 2 * TS, qkvl + 2 * TS, ah, al);

    dim3 gg(EE / 256, ROWS / 128);       // (4, 64)
    mma_gemm<false><<<gg, 256, gsmem>>>(ah, al, wh + 3ull*EE*EE, wl + 3ull*EE*EE,
                                        b_o, out, nullptr, nullptr);
}

// round 10
// speedup vs baseline: 1.0739x; 1.0217x over previous
#include <cuda_runtime.h>
#include <cuda_bf16.h>
#include <math.h>
#include <stdint.h>

#define BB 4
#define SS 2048
#define EE 1024
#define HH 16
#define DD 64
#define ROWS (BB*SS)          // 8192

#define NEG_INF (__int_as_float(0xff800000))

// ---------------- scratch (device globals: no runtime allocation) ----------
__device__ __align__(16) __nv_bfloat16 g_xh[ROWS*EE];
__device__ __align__(16) __nv_bfloat16 g_xl[ROWS*EE];
__device__ __align__(16) __nv_bfloat16 g_qkvh[3u*ROWS*EE];
__device__ __align__(16) __nv_bfloat16 g_qkvl[3u*ROWS*EE];
__device__ __align__(16) __nv_bfloat16 g_ah[ROWS*EE];
__device__ __align__(16) __nv_bfloat16 g_al[ROWS*EE];
__device__ __align__(16) __nv_bfloat16 g_wh[4u*EE*EE];
__device__ __align__(16) __nv_bfloat16 g_wl[4u*EE*EE];

#define N4X (ROWS*EE/4)       // 2097152 float4s in x
#define N4W (EE*EE/4)         // 262144 float4s per weight

// ---------------------------------------------------------------------------
// Fused fp32 -> bf16 hi/lo split for x + all 4 weights (single launch)
// ---------------------------------------------------------------------------
__global__ __launch_bounds__(256)
void split_all(const float4* __restrict__ x,
               const float4* __restrict__ w0, const float4* __restrict__ w1,
               const float4* __restrict__ w2, const float4* __restrict__ w3,
               uint2* __restrict__ xh, uint2* __restrict__ xl,
               uint2* __restrict__ wh, uint2* __restrict__ wl)
{
    int i = blockIdx.x * 256 + threadIdx.x;
    const float4* src; uint2 *dh, *dl;
    if (i < N4X) {
        src = x + i; dh = xh + i; dl = xl + i;
    } else {
        int j = i - N4X;
        int t = j >> 18;                 // N4W = 2^18
        int loc = j & (N4W - 1);
        const float4* ws[4] = {w0, w1, w2, w3};
        src = ws[t] + loc;
        dh = wh + (size_t)t * N4W + loc;
        dl = wl + (size_t)t * N4W + loc;
    }
    float4 v = *src;
    float vv[4] = {v.x, v.y, v.z, v.w};
    unsigned hu[4], lu[4];
    #pragma unroll
    for (int j = 0; j < 4; ++j) {
        __nv_bfloat16 h = __float2bfloat16(vv[j]);
        float r = vv[j] - __bfloat162float(h);
        __nv_bfloat16 l = __float2bfloat16(r);
        hu[j] = (unsigned)__bfloat16_as_ushort(h);
        lu[j] = (unsigned)__bfloat16_as_ushort(l);
    }
    uint2 ho, lv;
    ho.x = hu[0] | (hu[1] << 16); ho.y = hu[2] | (hu[3] << 16);
    lv.x = lu[0] | (lu[1] << 16); lv.y = lu[2] | (lu[3] << 16);
    *dh = ho; *dl = lv;
}

// ---------------------------------------------------------------------------
// mma.sync helpers
// ---------------------------------------------------------------------------
__device__ __forceinline__ void cp16(uint32_t saddr, const void* gptr) {
    asm volatile("cp.async.cg.shared.global [%0], [%1], 16;"
                 :: "r"(saddr), "l"(gptr));
}
__device__ __forceinline__ void cp_commit() {
    asm volatile("cp.async.commit_group;" ::: "memory");
}
__device__ __forceinline__ void ldsm4(uint32_t* r, uint32_t addr) {
    asm volatile("ldmatrix.sync.aligned.m8n8.x4.shared.b16 {%0,%1,%2,%3}, [%4];"
                 : "=r"(r[0]), "=r"(r[1]), "=r"(r[2]), "=r"(r[3]) : "r"(addr));
}
__device__ __forceinline__ void ldsm4t(uint32_t* r, uint32_t addr) {
    asm volatile("ldmatrix.sync.aligned.m8n8.x4.trans.shared.b16 {%0,%1,%2,%3}, [%4];"
                 : "=r"(r[0]), "=r"(r[1]), "=r"(r[2]), "=r"(r[3]) : "r"(addr));
}
__device__ __forceinline__ void mma16816(float* c, const uint32_t* a, const uint32_t* b) {
    asm volatile(
        "mma.sync.aligned.m16n8k16.row.col.f32.bf16.bf16.f32 "
        "{%0,%1,%2,%3}, {%4,%5,%6,%7}, {%8,%9}, {%0,%1,%2,%3};"
        : "+f"(c[0]), "+f"(c[1]), "+f"(c[2]), "+f"(c[3])
        : "r"(a[0]), "r"(a[1]), "r"(a[2]), "r"(a[3]), "r"(b[0]), "r"(b[1]));
}
__device__ __forceinline__ void splitpack(float a, float b, uint32_t& hi, uint32_t& lo) {
    __nv_bfloat16 ha = __float2bfloat16(a), hb = __float2bfloat16(b);
    uint32_t hh = (uint32_t)__bfloat16_as_ushort(ha) |
                  ((uint32_t)__bfloat16_as_ushort(hb) << 16);
    __nv_bfloat16 la = __float2bfloat16(a - __bfloat162float(ha));
    __nv_bfloat16 lb = __float2bfloat16(b - __bfloat162float(hb));
    uint32_t ll = (uint32_t)__bfloat16_as_ushort(la) |
                  ((uint32_t)__bfloat16_as_ushort(lb) << 16);
    hi = hh; lo = ll;
}

#define NKC (EE/64)          // 16 k-chunks

// ===========================================================================
// GEMM core (round-8 best): CTA tile 128x256, 8 warps (2x4), warp tile 64x64,
// 2-stage cp.async double buffer (96 KB/stage).
// ===========================================================================
#define OF_AL 16384
#define OF_BH 32768
#define OF_BL 65536
#define GSTAGE 98304

template<bool QKV>
__global__ __launch_bounds__(256, 1)
void mma_gemm(const __nv_bfloat16* __restrict__ Ah0, const __nv_bfloat16* __restrict__ Al0,
              const __nv_bfloat16* __restrict__ Wh0, const __nv_bfloat16* __restrict__ Wl0,
              const float* __restrict__ bias, float* __restrict__ C,
              __nv_bfloat16* __restrict__ Ch0, __nv_bfloat16* __restrict__ Cl0)
{
    extern __shared__ char smem[];
    const uint32_t sb = (uint32_t)__cvta_generic_to_shared(smem);
    const int K = EE, N = EE;

    const int tid = threadIdx.x;
    const int w = tid >> 5, lane = tid & 31;
    const int wm = w & 1, wn = w >> 1;               // 2 x 4 warp grid
    const int wsel = QKV ? (blockIdx.x >> 2) : 0;
    const int bm = blockIdx.y * 128;
    const int bn = QKV ? ((blockIdx.x & 3) * 256) : (blockIdx.x * 256);

    const __nv_bfloat16* Ahp = Ah0 + (size_t)bm * K;
    const __nv_bfloat16* Alp = Al0 + (size_t)bm * K;
    const __nv_bfloat16* Bhp = Wh0 + (size_t)wsel * EE * EE + (size_t)bn * K;
    const __nv_bfloat16* Blp = Wl0 + (size_t)wsel * EE * EE + (size_t)bn * K;
    __nv_bfloat16* Ch = QKV ? (Ch0 + (size_t)wsel * ROWS * EE) : nullptr;
    __nv_bfloat16* Cl = QKV ? (Cl0 + (size_t)wsel * ROWS * EE) : nullptr;

    const int r8 = lane & 7, g = lane >> 3;
    const int arow = wm * 64 + r8 + (g & 1) * 8;
    const int acolg = (g >> 1) * 16;
    const uint32_t axor = (uint32_t)((arow & 7) << 4);
    const int brow = wn * 64 + r8 + (g >> 1) * 8;
    const int bcolg = (g & 1) * 16;
    const uint32_t bxor = (uint32_t)((brow & 7) << 4);

    float acc[4][8][4];
    #pragma unroll
    for (int a = 0; a < 4; ++a)
        #pragma unroll
        for (int b = 0; b < 8; ++b)
            #pragma unroll
            for (int c = 0; c < 4; ++c) acc[a][b][c] = 0.f;

    auto load_stage = [&](int slot, int kc) {
        const uint32_t sbase = sb + (uint32_t)(slot * GSTAGE);
        #pragma unroll
        for (int i = 0; i < 24; ++i) {
            int idx = tid + i * 256;
            const __nv_bfloat16* src;
            uint32_t toff; int local;
            if (i < 4)       { local = idx;        src = Ahp; toff = 0; }
            else if (i < 8)  { local = idx - 1024; src = Alp; toff = OF_AL; }
            else if (i < 16) { local = idx - 2048; src = Bhp; toff = OF_BH; }
            else             { local = idx - 4096; src = Blp; toff = OF_BL; }
            int row = local >> 3, s8 = local & 7;
            cp16(sbase + toff + (uint32_t)(row * 128 + ((s8 * 16) ^ ((row & 7) << 4))),
                 src + (size_t)row * K + kc * 64 + s8 * 8);
        }
        cp_commit();
    };

    load_stage(0, 0);

    for (int kc = 0; kc < NKC; ++kc) {
        if (kc + 1 < NKC) {
            load_stage((kc + 1) & 1, kc + 1);
            asm volatile("cp.async.wait_group 1;" ::: "memory");
        } else {
            asm volatile("cp.async.wait_group 0;" ::: "memory");
        }
        __syncthreads();

        const uint32_t stg = sb + (uint32_t)((kc & 1) * GSTAGE);

        #pragma unroll
        for (int ks = 0; ks < 4; ++ks) {
            uint32_t aH[4][4], aL[4][4];
            const uint32_t colA = (uint32_t)(ks * 32 + acolg) ^ axor;
            const uint32_t colB = (uint32_t)(ks * 32 + bcolg) ^ bxor;
            #pragma unroll
            for (int mf = 0; mf < 4; ++mf) {
                const uint32_t ro = (uint32_t)((arow + mf * 16) * 128) + colA;
                ldsm4(aH[mf], stg + ro);
                ldsm4(aL[mf], stg + OF_AL + ro);
            }
            #pragma unroll
            for (int nf2 = 0; nf2 < 4; ++nf2) {
                uint32_t bH[4], bL[4];
                const uint32_t ro = (uint32_t)((brow + nf2 * 16) * 128) + colB;
                ldsm4(bH, stg + OF_BH + ro);
                ldsm4(bL, stg + OF_BL + ro);
                #pragma unroll
                for (int mf = 0; mf < 4; ++mf)
                    #pragma unroll
                    for (int j = 0; j < 2; ++j) {
                        float* c = acc[mf][nf2 * 2 + j];
                        mma16816(c, aH[mf], &bH[j * 2]);
                        mma16816(c, aH[mf], &bL[j * 2]);
                        mma16816(c, aL[mf], &bH[j * 2]);
                    }
            }
        }
        __syncthreads();
    }

    const int row0 = bm + wm * 64 + (lane >> 2);
    const int col0 = bn + wn * 64 + (lane & 3) * 2;
    #pragma unroll
    for (int mf = 0; mf < 4; ++mf)
        #pragma unroll
        for (int nf = 0; nf < 8; ++nf) {
            const int r = row0 + mf * 16;
            const int col = col0 + nf * 8;
            if (QKV) {
                uint32_t h0, l0, h1, l1;
                splitpack(acc[mf][nf][0], acc[mf][nf][1], h0, l0);
                splitpack(acc[mf][nf][2], acc[mf][nf][3], h1, l1);
                *(uint32_t*)&Ch[(size_t)r * N + col]       = h0;
                *(uint32_t*)&Cl[(size_t)r * N + col]       = l0;
                *(uint32_t*)&Ch[(size_t)(r + 8) * N + col] = h1;
                *(uint32_t*)&Cl[(size_t)(r + 8) * N + col] = l1;
            } else {
                float b0 = bias[col], b1 = bias[col + 1];
                float2 v0, v1;
                v0.x = acc[mf][nf][0] + b0; v0.y = acc[mf][nf][1] + b1;
                v1.x = acc[mf][nf][2] + b0; v1.y = acc[mf][nf][3] + b1;
                *(float2*)&C[(size_t)r * N + col]       = v0;
                *(float2*)&C[(size_t)(r + 8) * N + col] = v1;
            }
        }
}

// ---------------------------------------------------------------------------
// Tensor-core causal flash attention, triple-buffered KV (one sync / chunk).
// CTA: 256 q rows, 512 threads. smem: Qh[32K] Ql[32K] | 3 x (Kh,Kl,Vh,Vl 4x8K)
// = 160 KB.
// ---------------------------------------------------------------------------
#define FKVB 32768

__global__ __launch_bounds__(512, 1)
void flash_mma(const __nv_bfloat16* __restrict__ Qh, const __nv_bfloat16* __restrict__ Ql,
               const __nv_bfloat16* __restrict__ Kh, const __nv_bfloat16* __restrict__ Kl,
               const __nv_bfloat16* __restrict__ Vh, const __nv_bfloat16* __restrict__ Vl,
               __nv_bfloat16* __restrict__ Oh, __nv_bfloat16* __restrict__ Ol)
{
    extern __shared__ char smem[];
    const uint32_t sb = (uint32_t)__cvta_generic_to_shared(smem);
    const int tid = threadIdx.x, w = tid >> 5, lane = tid & 31;
    const int qt = (int)(gridDim.x - 1 - blockIdx.x);   // longest first
    const int bh = blockIdx.y, b = bh >> 4, h = bh & 15;
    const size_t gbase = (size_t)(b * SS) * EE + h * 64;

    const __nv_bfloat16* kv[4] = { Kh, Kl, Vh, Vl };

    auto load_kv = [&](int chunk) {
        const uint32_t bufb = sb + 65536 + (uint32_t)((chunk % 3) * FKVB);
        #pragma unroll
        for (int i = 0; i < 4; ++i) {
            int idx = tid + i * 512;
            int t = idx >> 9, rr = (idx & 511) >> 3, s8 = idx & 7;
            cp16(bufb + t * 8192 + rr * 128 + (uint32_t)((s8 * 16) ^ ((rr & 7) << 4)),
                 kv[t] + gbase + (size_t)(chunk * 64 + rr) * EE + s8 * 8);
        }
    };

    // group 0: Q tile + chunk 0 ; group 1: chunk 1
    #pragma unroll
    for (int i = 0; i < 8; ++i) {
        int idx = tid + i * 512;
        int t = idx >> 11, rr = (idx & 2047) >> 3, s8 = idx & 7;
        const __nv_bfloat16* src = (t ? Ql : Qh) + gbase + (size_t)(qt * 256 + rr) * EE + s8 * 8;
        cp16(sb + t * 32768 + rr * 128 + (uint32_t)((s8 * 16) ^ ((rr & 7) << 4)), src);
    }
    load_kv(0);
    cp_commit();
    load_kv(1);          // nch >= 4 always, chunk 1 exists
    cp_commit();

    const int r8 = lane & 7, g = lane >> 3;
    const int arow = w * 16 + r8 + (g & 1) * 8;
    const uint32_t axor = (uint32_t)((arow & 7) << 4);
    const int acolg = (g >> 1) * 16;
    const int brow = r8 + (g >> 1) * 8;
    const uint32_t bxor = (uint32_t)((brow & 7) << 4);
    const int bcolg = (g & 1) * 16;
    const int vrow = r8 + (g & 1) * 8;
    const uint32_t vxor = (uint32_t)((vrow & 7) << 4);
    const int vcolg = (g >> 1) * 16;

    float oacc[8][4];
    #pragma unroll
    for (int j = 0; j < 8; ++j)
        #pragma unroll
        for (int e = 0; e < 4; ++e) oacc[j][e] = 0.f;
    float m0 = NEG_INF, m1 = NEG_INF, l0 = 0.f, l1 = 0.f;

    const int nch = 4 * qt + 4;
    const int wminrow = qt * 256 + w * 16;

    for (int c = 0; c < nch; ++c) {
        // groups pending after this wait: at most {c+1} -> group c complete
        asm volatile("cp.async.wait_group 1;" ::: "memory");
        __syncthreads();     // all warps done with chunk c-1; buffer (c+2)%3 free

        if (c + 2 < nch) load_kv(c + 2);
        cp_commit();         // empty group in tail keeps the count consistent

        if (c * 64 <= wminrow + 15) {
            const uint32_t bufb = sb + 65536 + (uint32_t)((c % 3) * FKVB);
            float sacc[8][4];
            #pragma unroll
            for (int j = 0; j < 8; ++j)
                #pragma unroll
                for (int e = 0; e < 4; ++e) sacc[j][e] = 0.f;

            #pragma unroll
            for (int ks = 0; ks < 4; ++ks) {
                uint32_t aH[4], aL[4];
                const uint32_t ao = (uint32_t)(arow * 128) + ((uint32_t)(ks * 32 + acolg) ^ axor);
                ldsm4(aH, sb + ao);
                ldsm4(aL, sb + 32768 + ao);
                const uint32_t colB = (uint32_t)(ks * 32 + bcolg) ^ bxor;
                #pragma unroll
                for (int nf2 = 0; nf2 < 4; ++nf2) {
                    uint32_t bH[4], bL[4];
                    const uint32_t ro = (uint32_t)((brow + nf2 * 16) * 128) + colB;
                    ldsm4(bH, bufb + ro);
                    ldsm4(bL, bufb + 8192 + ro);
                    #pragma unroll
                    for (int j = 0; j < 2; ++j) {
                        float* cc = sacc[nf2 * 2 + j];
                        mma16816(cc, aH, &bH[j * 2]);
                        mma16816(cc, aH, &bL[j * 2]);
                        mma16816(cc, aL, &bH[j * 2]);
                    }
                }
            }

            const int row0 = wminrow + (lane >> 2);
            if (c * 64 + 63 > wminrow) {
                #pragma unroll
                for (int j = 0; j < 8; ++j) {
                    int col = c * 64 + j * 8 + (lane & 3) * 2;
                    if (col     > row0)     sacc[j][0] = NEG_INF;
                    if (col + 1 > row0)     sacc[j][1] = NEG_INF;
                    if (col     > row0 + 8) sacc[j][2] = NEG_INF;
                    if (col + 1 > row0 + 8) sacc[j][3] = NEG_INF;
                }
            }
            float t0 = NEG_INF, t1 = NEG_INF;
            #pragma unroll
            for (int j = 0; j < 8; ++j) {
                sacc[j][0] *= 0.125f; sacc[j][1] *= 0.125f;
                sacc[j][2] *= 0.125f; sacc[j][3] *= 0.125f;
                t0 = fmaxf(t0, fmaxf(sacc[j][0], sacc[j][1]));
                t1 = fmaxf(t1, fmaxf(sacc[j][2], sacc[j][3]));
            }
            t0 = fmaxf(t0, __shfl_xor_sync(0xffffffffu, t0, 1));
            t0 = fmaxf(t0, __shfl_xor_sync(0xffffffffu, t0, 2));
            t1 = fmaxf(t1, __shfl_xor_sync(0xffffffffu, t1, 1));
            t1 = fmaxf(t1, __shfl_xor_sync(0xffffffffu, t1, 2));

            const float mn0 = fmaxf(m0, t0), mn1 = fmaxf(m1, t1);
            const float cr0 = __expf(m0 - mn0), cr1 = __expf(m1 - mn1);
            float s0 = 0.f, s1 = 0.f;
            #pragma unroll
            for (int j = 0; j < 8; ++j) {
                float p0 = __expf(sacc[j][0] - mn0); sacc[j][0] = p0; s0 += p0;
                float p1 = __expf(sacc[j][1] - mn0); sacc[j][1] = p1; s0 += p1;
                float p2 = __expf(sacc[j][2] - mn1); sacc[j][2] = p2; s1 += p2;
                float p3 = __expf(sacc[j][3] - mn1); sacc[j][3] = p3; s1 += p3;
            }
            s0 += __shfl_xor_sync(0xffffffffu, s0, 1);
            s0 += __shfl_xor_sync(0xffffffffu, s0, 2);
            s1 += __shfl_xor_sync(0xffffffffu, s1, 1);
            s1 += __shfl_xor_sync(0xffffffffu, s1, 2);
            l0 = l0 * cr0 + s0; l1 = l1 * cr1 + s1;
            m0 = mn0; m1 = mn1;
            #pragma unroll
            for (int j = 0; j < 8; ++j) {
                oacc[j][0] *= cr0; oacc[j][1] *= cr0;
                oacc[j][2] *= cr1; oacc[j][3] *= cr1;
            }

            #pragma unroll
            for (int ks = 0; ks < 4; ++ks) {
                uint32_t aPh[4], aPl[4];
                splitpack(sacc[2*ks][0],   sacc[2*ks][1],   aPh[0], aPl[0]);
                splitpack(sacc[2*ks][2],   sacc[2*ks][3],   aPh[1], aPl[1]);
                splitpack(sacc[2*ks+1][0], sacc[2*ks+1][1], aPh[2], aPl[2]);
                splitpack(sacc[2*ks+1][2], sacc[2*ks+1][3], aPh[3], aPl[3]);
                const uint32_t rbase = (uint32_t)((ks * 16 + vrow) * 128);
                #pragma unroll
                for (int nf2 = 0; nf2 < 4; ++nf2) {
                    uint32_t vH[4], vL[4];
                    const uint32_t vo = rbase + ((uint32_t)(nf2 * 32 + vcolg) ^ vxor);
                    ldsm4t(vH, bufb + 16384 + vo);
                    ldsm4t(vL, bufb + 24576 + vo);
                    #pragma unroll
                    for (int j = 0; j < 2; ++j) {
                        float* cc = oacc[nf2 * 2 + j];
                        mma16816(cc, aPh, &vH[j * 2]);
                        mma16816(cc, aPh, &vL[j * 2]);
                        mma16816(cc, aPl, &vH[j * 2]);
                    }
                }
            }
        }
    }

    const float inv0 = 1.f / l0, inv1 = 1.f / l1;
    const int orow = qt * 256 + w * 16 + (lane >> 2);
    const int ocol = (lane & 3) * 2;
    #pragma unroll
    for (int j = 0; j < 8; ++j) {
        uint32_t h0, lo0, h1, lo1;
        splitpack(oacc[j][0] * inv0, oacc[j][1] * inv0, h0, lo0);
        splitpack(oacc[j][2] * inv1, oacc[j][3] * inv1, h1, lo1);
        size_t a0 = gbase + (size_t)orow * EE + j * 8 + ocol;
        size_t a1 = a0 + (size_t)8 * EE;
        *(uint32_t*)&Oh[a0] = h0; *(uint32_t*)&Ol[a0] = lo0;
        *(uint32_t*)&Oh[a1] = h1; *(uint32_t*)&Ol[a1] = lo1;
    }
}

// ---------------------------------------------------------------------------
extern "C" void kernel_launch(void* const* d_in, const int* in_sizes, int n_in,
                              void* d_out, int out_size)
{
    const float* x   = (const float*)d_in[0];
    const float* w_q = (const float*)d_in[2];
    const float* w_k = (const float*)d_in[3];
    const float* w_v = (const float*)d_in[4];
    const float* w_o = (const float*)d_in[5];
    const float* b_o = (const float*)d_in[6];
    float* out = (float*)d_out;

    __nv_bfloat16 *xh, *xl, *qkvh, *qkvl, *ah, *al, *wh, *wl;
    cudaGetSymbolAddress((void**)&xh,   g_xh);
    cudaGetSymbolAddress((void**)&xl,   g_xl);
    cudaGetSymbolAddress((void**)&qkvh, g_qkvh);
    cudaGetSymbolAddress((void**)&qkvl, g_qkvl);
    cudaGetSymbolAddress((void**)&ah,   g_ah);
    cudaGetSymbolAddress((void**)&al,   g_al);
    cudaGetSymbolAddress((void**)&wh,   g_wh);
    cudaGetSymbolAddress((void**)&wl,   g_wl);

    // 1) one fused split launch (x + 4 weights)
    const int nblk = (N4X + 4 * N4W) / 256;   // 12288
    split_all<<<nblk, 256>>>((const float4*)x,
                             (const float4*)w_q, (const float4*)w_k,
                             (const float4*)w_v, (const float4*)w_o,
                             (uint2*)xh, (uint2*)xl, (uint2*)wh, (uint2*)wl);

    // 2) fused QKV GEMM
    const int gsmem = 2 * GSTAGE;        // 196608
    cudaFuncSetAttribute(mma_gemm<true>,  cudaFuncAttributeMaxDynamicSharedMemorySize, gsmem);
    cudaFuncSetAttribute(mma_gemm<false>, cudaFuncAttributeMaxDynamicSharedMemorySize, gsmem);
    dim3 gq(3 * EE / 256, ROWS / 128);   // (12, 64)
    mma_gemm<true><<<gq, 256, gsmem>>>(xh, xl, wh, wl, nullptr, nullptr, qkvh, qkvl);

    // 3) flash attention
    const size_t TS = (size_t)ROWS * EE;
    const int fsmem = 65536 + 3 * FKVB;  // 163840
    cudaFuncSetAttribute(flash_mma, cudaFuncAttributeMaxDynamicSharedMemorySize, fsmem);
    dim3 fgrid(SS / 256, BB * HH);
    flash_mma<<<fgrid, 512, fsmem>>>(qkvh, qkvl, qkvh + TS, qkvl + TS,
                                     qkvh + 2 * TS, qkvl + 2 * TS, ah, al);

    // 4) O projection
    dim3 gg(EE / 256, ROWS / 128);       // (4, 64)
    mma_gemm<false><<<gg, 256, gsmem>>>(ah, al, wh + 3ull*EE*EE, wl + 3ull*EE*EE,
                                        b_o, out, nullptr, nullptr);
}